// round 4
// baseline (speedup 1.0000x reference)
#include <cuda_runtime.h>
#include <cuda_bf16.h>
#include <cstdint>

#define NN 256
#define FF 16
#define HH 2048
#define PP 16
#define EE 32768

// Scratch (device globals; allocation is forbidden).
__device__ int4  d_A4[NN * NN / 4];   // dense count matrix (incl. self-loops), 256 KB
__device__ float d_dinv[NN];
__device__ float d_agg[NN * FF];      // dinv[d] * (A @ (dinv*x))[d,f]
__device__ float d_outh[NN * HH];     // agg @ W + b   (2 MB)

// ---------------------------------------------------------------------------
// K1: dense edge-count matrix + self-loops + dinv = rsqrt(rowsum).
// 8 blocks; block b owns dst rows [b*32, b*32+32) via a 32KB smem histogram.
// Edge dtype probed at runtime: harness may deliver int64->int32-cast data.
// ---------------------------------------------------------------------------
__global__ __launch_bounds__(256) void k_count(const void* __restrict__ ei_raw) {
    __shared__ int hist[32 * NN];     // 32 rows x 256 cols = 32 KB
    int t = threadIdx.x;
    int b = blockIdx.x;
    int row_lo = b * 32;

    const int*       e32 = (const int*)ei_raw;
    const long long* e64 = (const long long*)ei_raw;

    // dtype probe: int64 node ids (<256) have zero high words at odd int32
    // slots; live int32 ids there are ~never all zero across 16 probes.
    int probe = 0;
#pragma unroll
    for (int k = 0; k < 16; k++) probe |= e32[2 * k + 1];
    const bool is64 = (probe == 0);

    // zero histogram
#pragma unroll
    for (int i = 0; i < 32; i++) hist[t + i * 256] = 0;
    __syncthreads();

    // self-loops
    if (t < 32) hist[t * NN + (row_lo + t)] = 1;
    __syncthreads();

    // scan all edges; keep those whose dst falls in this block's row range
    for (int e = t; e < EE; e += 256) {
        int src, dst;
        if (is64) { src = (int)e64[e]; dst = (int)e64[EE + e]; }
        else      { src = e32[e];      dst = e32[EE + e];      }
        int lr = dst - row_lo;
        if ((unsigned)lr < 32u && (unsigned)src < (unsigned)NN)
            atomicAdd(&hist[lr * NN + src], 1);
    }
    __syncthreads();

    // write rows to global (typed int4 array -> guaranteed aligned)
    const int4* sh4 = reinterpret_cast<const int4*>(hist);
#pragma unroll
    for (int i = 0; i < 8; i++) {
        int idx = t + i * 256;        // 2048 int4 per block
        d_A4[b * 2048 + idx] = sh4[idx];
    }

    // degree = row sum; dinv = rsqrt(deg) (deg >= 1 due to self-loop)
    int wid = t >> 5, lane = t & 31;
#pragma unroll
    for (int r = 0; r < 4; r++) {
        int lr = wid * 4 + r;
        int s = 0;
#pragma unroll
        for (int k = 0; k < 8; k++) s += hist[lr * NN + lane + k * 32];
#pragma unroll
        for (int off = 16; off > 0; off >>= 1) s += __shfl_down_sync(0xffffffffu, s, off);
        if (lane == 0) d_dinv[row_lo + lr] = rsqrtf((float)s);
    }
}

// ---------------------------------------------------------------------------
// K2: agg[d,f] = dinv[d] * sum_s A[d,s] * (dinv[s]*x[s,f])
// 16 blocks x 16 nodes. Full scaled-x and 16 A-rows staged in smem.
// ---------------------------------------------------------------------------
__global__ __launch_bounds__(256) void k_agg(const float* __restrict__ x) {
    __shared__ float sy[NN * FF];     // 16 KB (dinv-scaled x)
    __shared__ int   sA[16 * NN];     // 16 KB
    int t = threadIdx.x;
    int b = blockIdx.x;

    // stage y = dinv * x  (float4 j covers row j>>2; FF=16 -> 4 float4/row)
    const float4* gx4 = reinterpret_cast<const float4*>(x);
    float4* sy4 = reinterpret_cast<float4*>(sy);
#pragma unroll
    for (int i = 0; i < 4; i++) {
        int j = t + i * 256;          // 1024 float4
        float dv = d_dinv[j >> 2];
        float4 v = gx4[j];
        v.x *= dv; v.y *= dv; v.z *= dv; v.w *= dv;
        sy4[j] = v;
    }

    // stage 16 A-rows (1024 int4)
    int4* sA4 = reinterpret_cast<int4*>(sA);
#pragma unroll
    for (int i = 0; i < 4; i++) {
        int j = t + i * 256;
        sA4[j] = d_A4[b * 1024 + j];
    }
    __syncthreads();

    int dl = t >> 4;                  // local node 0..15
    int f  = t & 15;
    float acc = 0.0f;
#pragma unroll 8
    for (int s = 0; s < NN; s++)
        acc += (float)sA[dl * NN + s] * sy[s * FF + f];

    int d = b * 16 + dl;
    d_agg[d * FF + f] = d_dinv[d] * acc;
}

// ---------------------------------------------------------------------------
// K3: out[n,h] = b[h] + sum_f agg[n,f] * W[f,h]
// grid (8 h-tiles of 256, 16 node chunks of 16)
// ---------------------------------------------------------------------------
__global__ __launch_bounds__(256) void k_out(const float* __restrict__ W,
                                             const float* __restrict__ bias) {
    __shared__ float sagg[256];       // 16 nodes x 16 f
    int t  = threadIdx.x;
    int ht = blockIdx.x;
    int nc = blockIdx.y;

    sagg[t] = d_agg[nc * 256 + t];
    __syncthreads();

    int h = ht * 256 + t;
    float wc[FF];
#pragma unroll
    for (int f = 0; f < FF; f++) wc[f] = W[f * HH + h];
    float bh = bias[h];

#pragma unroll
    for (int nl = 0; nl < 16; nl++) {
        float v = bh;
#pragma unroll
        for (int f = 0; f < FF; f++) v = fmaf(sagg[nl * FF + f], wc[f], v);
        d_outh[(nc * 16 + nl) * HH + h] = v;
    }
}

// ---------------------------------------------------------------------------
// K4: q[n,p] = sum_h out[n,h] * Wq[n,h,p] + bq[n,p]
// one block per node; coalesced float4 streaming of Wq (the 33.5 MB).
// ---------------------------------------------------------------------------
__global__ __launch_bounds__(256) void k_final(const float* __restrict__ Wq,
                                               const float* __restrict__ bq,
                                               float* __restrict__ q) {
    __shared__ float sred[8 * PP];
    int n = blockIdx.x;
    int t = threadIdx.x;

    float acc[PP];
#pragma unroll
    for (int p = 0; p < PP; p++) acc[p] = 0.0f;

    const float* wqn = Wq + (size_t)n * HH * PP;
#pragma unroll
    for (int r = 0; r < HH / 256; r++) {
        int h = r * 256 + t;
        float oh = d_outh[n * HH + h];
        const float4* wq4 = reinterpret_cast<const float4*>(wqn + (size_t)h * PP);
        float4 a0 = wq4[0], a1 = wq4[1], a2 = wq4[2], a3 = wq4[3];
        acc[0]  = fmaf(oh, a0.x, acc[0]);  acc[1]  = fmaf(oh, a0.y, acc[1]);
        acc[2]  = fmaf(oh, a0.z, acc[2]);  acc[3]  = fmaf(oh, a0.w, acc[3]);
        acc[4]  = fmaf(oh, a1.x, acc[4]);  acc[5]  = fmaf(oh, a1.y, acc[5]);
        acc[6]  = fmaf(oh, a1.z, acc[6]);  acc[7]  = fmaf(oh, a1.w, acc[7]);
        acc[8]  = fmaf(oh, a2.x, acc[8]);  acc[9]  = fmaf(oh, a2.y, acc[9]);
        acc[10] = fmaf(oh, a2.z, acc[10]); acc[11] = fmaf(oh, a2.w, acc[11]);
        acc[12] = fmaf(oh, a3.x, acc[12]); acc[13] = fmaf(oh, a3.y, acc[13]);
        acc[14] = fmaf(oh, a3.z, acc[14]); acc[15] = fmaf(oh, a3.w, acc[15]);
    }

#pragma unroll
    for (int off = 16; off > 0; off >>= 1) {
#pragma unroll
        for (int p = 0; p < PP; p++)
            acc[p] += __shfl_down_sync(0xffffffffu, acc[p], off);
    }
    int wid  = t >> 5;
    int lane = t & 31;
    if (lane == 0) {
#pragma unroll
        for (int p = 0; p < PP; p++) sred[wid * PP + p] = acc[p];
    }
    __syncthreads();
    if (t < PP) {
        float s = bq[n * PP + t];
#pragma unroll
        for (int w = 0; w < 8; w++) s += sred[w * PP + t];
        q[n * PP + t] = s;
    }
}

// ---------------------------------------------------------------------------
extern "C" void kernel_launch(void* const* d_in, const int* in_sizes, int n_in,
                              void* d_out, int out_size) {
    const float* x    = (const float*)d_in[0];      // [256,16]
    const void*  ei   = d_in[1];                    // [2,32768] int64 OR int32
    const float* W    = (const float*)d_in[2];      // [16,2048]
    const float* bias = (const float*)d_in[3];      // [2048]
    const float* Wq   = (const float*)d_in[4];      // [256,2048,16]
    const float* bq   = (const float*)d_in[5];      // [256,16]
    float*       q    = (float*)d_out;              // [256,16]

    k_count<<<8, 256>>>(ei);
    k_agg<<<16, 256>>>(x);
    k_out<<<dim3(8, 16), 256>>>(W, bias);
    k_final<<<NN, 256>>>(Wq, bq, q);
}

// round 6
// speedup vs baseline: 1.0920x; 1.0920x over previous
#include <cuda_runtime.h>
#include <cuda_bf16.h>
#include <cstdint>

#define NN 256
#define FF 16
#define HH 2048
#define PP 16
#define EE 32768

// Scratch (device globals; allocation is forbidden).
__device__ int4  d_A4[NN * NN / 4];   // dense count matrix (incl. self-loops), 256 KB
__device__ float d_dinv[NN];
__device__ float d_outh[NN * HH];     // agg @ W + b   (2 MB)

// ---------------------------------------------------------------------------
// K1: dense edge-count matrix + self-loops + dinv = rsqrt(rowsum).
// 32 blocks; block b owns dst rows [b*8, b*8+8) via an 8KB smem histogram.
// Edge dtype probed at runtime (harness delivers int64 cast to int32).
// ---------------------------------------------------------------------------
__global__ __launch_bounds__(256) void k_count(const void* __restrict__ ei_raw) {
    __shared__ int hist[8 * NN];      // 8 rows x 256 cols = 8 KB
    int t = threadIdx.x;
    int b = blockIdx.x;
    int row_lo = b * 8;

    const int*       e32 = (const int*)ei_raw;
    const long long* e64 = (const long long*)ei_raw;

    // dtype probe: int64 ids (<256) have zero high words at odd int32 slots.
    int probe = 0;
#pragma unroll
    for (int k = 0; k < 16; k++) probe |= e32[2 * k + 1];
    const bool is64 = (probe == 0);

#pragma unroll
    for (int i = 0; i < 8; i++) hist[t + i * 256] = 0;
    __syncthreads();

    if (t < 8) hist[t * NN + (row_lo + t)] = 1;   // self-loops
    __syncthreads();

    for (int e = t; e < EE; e += 256) {
        int src, dst;
        if (is64) { src = (int)e64[e]; dst = (int)e64[EE + e]; }
        else      { src = e32[e];      dst = e32[EE + e];      }
        int lr = dst - row_lo;
        if ((unsigned)lr < 8u && (unsigned)src < (unsigned)NN)
            atomicAdd(&hist[lr * NN + src], 1);
    }
    __syncthreads();

    // write 8 rows = 512 int4 with 256 threads (TWO iterations — R5 bug fix)
    const int4* sh4 = reinterpret_cast<const int4*>(hist);
#pragma unroll
    for (int i = 0; i < 2; i++)
        d_A4[b * 512 + t + i * 256] = sh4[t + i * 256];

    // dinv: warp w sums row w (deg >= 1 due to self-loop)
    int wid = t >> 5, lane = t & 31;
    if (wid < 8) {
        int s = 0;
#pragma unroll
        for (int k = 0; k < 8; k++) s += hist[wid * NN + lane + k * 32];
#pragma unroll
        for (int off = 16; off > 0; off >>= 1) s += __shfl_down_sync(0xffffffffu, s, off);
        if (lane == 0) d_dinv[row_lo + wid] = rsqrtf((float)s);
    }
}

// ---------------------------------------------------------------------------
// K2 (fused): recompute agg for this block's 16-node chunk, then
// out[n,h] = b[h] + sum_f agg[n,f]*W[f,h]. Block (ht, nc), grid (8, 16).
// ht==0 blocks also pre-initialize q = bq for K3's atomic accumulation.
// ---------------------------------------------------------------------------
__global__ __launch_bounds__(256) void k_fused(const float* __restrict__ x,
                                               const float* __restrict__ W,
                                               const float* __restrict__ bias,
                                               const float* __restrict__ bq,
                                               float* __restrict__ q) {
    __shared__ float sy[NN * FF];     // 16 KB (dinv-scaled x)
    __shared__ int   sA[16 * NN];     // 16 KB
    __shared__ float sagg[256];       // 1 KB (16 nodes x 16 f)
    int t  = threadIdx.x;
    int ht = blockIdx.x;
    int nc = blockIdx.y;

    // q init (nc covers exactly 16 nodes x 16 p = 256 values)
    if (ht == 0) q[nc * 256 + t] = bq[nc * 256 + t];

    // stage y = dinv * x  (float4 j covers row j>>2; FF=16 -> 4 float4/row)
    const float4* gx4 = reinterpret_cast<const float4*>(x);
    float4* sy4 = reinterpret_cast<float4*>(sy);
#pragma unroll
    for (int i = 0; i < 4; i++) {
        int j = t + i * 256;
        float dv = d_dinv[j >> 2];
        float4 v = gx4[j];
        v.x *= dv; v.y *= dv; v.z *= dv; v.w *= dv;
        sy4[j] = v;
    }
    // stage this chunk's 16 A-rows (1024 int4)
    int4* sA4 = reinterpret_cast<int4*>(sA);
#pragma unroll
    for (int i = 0; i < 4; i++) {
        int j = t + i * 256;
        sA4[j] = d_A4[nc * 1024 + j];
    }
    __syncthreads();

    // agg[dl,f] = dinv[d] * sum_s A[dl,s]*sy[s,f]
    {
        int dl = t >> 4, f = t & 15;
        float acc = 0.0f;
#pragma unroll 8
        for (int s = 0; s < NN; s++)
            acc += (float)sA[dl * NN + s] * sy[s * FF + f];
        sagg[t] = d_dinv[nc * 16 + dl] * acc;
    }
    __syncthreads();

    // out for 16 nodes x 256 h
    int h = ht * 256 + t;
    float wc[FF];
#pragma unroll
    for (int f = 0; f < FF; f++) wc[f] = W[f * HH + h];
    float bh = bias[h];
#pragma unroll
    for (int nl = 0; nl < 16; nl++) {
        float v = bh;
#pragma unroll
        for (int f = 0; f < FF; f++) v = fmaf(sagg[nl * FF + f], wc[f], v);
        d_outh[(nc * 16 + nl) * HH + h] = v;
    }
}

// ---------------------------------------------------------------------------
// K3: q[n,p] += sum_h out[n,h] * Wq[n,h,p]
// 512 blocks (node, H-half) x 512 threads -> enough warps in flight to
// saturate DRAM/L2 on the 33.5 MB Wq stream. Partials via atomicAdd.
// ---------------------------------------------------------------------------
__global__ __launch_bounds__(512) void k_final(const float* __restrict__ Wq,
                                               float* __restrict__ q) {
    __shared__ float sred[16 * PP];
    int n    = blockIdx.x >> 1;
    int half = blockIdx.x & 1;
    int t    = threadIdx.x;

    float acc[PP];
#pragma unroll
    for (int p = 0; p < PP; p++) acc[p] = 0.0f;

    const float* wqn = Wq + (size_t)n * HH * PP;
#pragma unroll
    for (int r = 0; r < 2; r++) {
        int h = half * 1024 + r * 512 + t;
        float oh = d_outh[n * HH + h];
        const float4* wq4 = reinterpret_cast<const float4*>(wqn + (size_t)h * PP);
        float4 a0 = wq4[0], a1 = wq4[1], a2 = wq4[2], a3 = wq4[3];
        acc[0]  = fmaf(oh, a0.x, acc[0]);  acc[1]  = fmaf(oh, a0.y, acc[1]);
        acc[2]  = fmaf(oh, a0.z, acc[2]);  acc[3]  = fmaf(oh, a0.w, acc[3]);
        acc[4]  = fmaf(oh, a1.x, acc[4]);  acc[5]  = fmaf(oh, a1.y, acc[5]);
        acc[6]  = fmaf(oh, a1.z, acc[6]);  acc[7]  = fmaf(oh, a1.w, acc[7]);
        acc[8]  = fmaf(oh, a2.x, acc[8]);  acc[9]  = fmaf(oh, a2.y, acc[9]);
        acc[10] = fmaf(oh, a2.z, acc[10]); acc[11] = fmaf(oh, a2.w, acc[11]);
        acc[12] = fmaf(oh, a3.x, acc[12]); acc[13] = fmaf(oh, a3.y, acc[13]);
        acc[14] = fmaf(oh, a3.z, acc[14]); acc[15] = fmaf(oh, a3.w, acc[15]);
    }

#pragma unroll
    for (int off = 16; off > 0; off >>= 1) {
#pragma unroll
        for (int p = 0; p < PP; p++)
            acc[p] += __shfl_down_sync(0xffffffffu, acc[p], off);
    }
    int wid  = t >> 5;
    int lane = t & 31;
    if (lane == 0) {
#pragma unroll
        for (int p = 0; p < PP; p++) sred[wid * PP + p] = acc[p];
    }
    __syncthreads();
    if (t < PP) {
        float s = 0.0f;
#pragma unroll
        for (int w = 0; w < 16; w++) s += sred[w * PP + t];
        atomicAdd(&q[n * PP + t], s);
    }
}

// ---------------------------------------------------------------------------
extern "C" void kernel_launch(void* const* d_in, const int* in_sizes, int n_in,
                              void* d_out, int out_size) {
    const float* x    = (const float*)d_in[0];      // [256,16]
    const void*  ei   = d_in[1];                    // [2,32768] (int64 cast to int32)
    const float* W    = (const float*)d_in[2];      // [16,2048]
    const float* bias = (const float*)d_in[3];      // [2048]
    const float* Wq   = (const float*)d_in[4];      // [256,2048,16]
    const float* bq   = (const float*)d_in[5];      // [256,16]
    float*       q    = (float*)d_out;              // [256,16]

    k_count<<<32, 256>>>(ei);
    k_fused<<<dim3(8, 16), 256>>>(x, W, bias, bq, q);
    k_final<<<2 * NN, 512>>>(Wq, q);
}